// round 3
// baseline (speedup 1.0000x reference)
#include <cuda_runtime.h>
#include <cstdint>
#include <cstddef>

#define B_   2048
#define T_   200
#define DI_  64
#define H_   128
#define G_   384
#define DU_  128
#define DIN_ 25728
#define BT_  (B_*T_)

// ---------------- device-global scratch ----------------
__device__ float g_xg[(size_t)BT_ * G_];     // gate preactivations (reused by both layers)
__device__ float g_y[(size_t)BT_ * H_];      // layer-0 GRU output
__device__ float g_cat[(size_t)B_ * DIN_];   // [user | flat(y1)]
__device__ float g_a1[(size_t)B_ * 1024];
__device__ float g_a2[(size_t)B_ * 512];

// ---------------- helpers ----------------
__device__ __forceinline__ float t32(float x) {
    uint32_t u; asm("cvt.rna.tf32.f32 %0, %1;" : "=r"(u) : "f"(x));
    return __uint_as_float(u);
}
__device__ __forceinline__ void mma_tf32(float* d, const float* a, const float* b) {
    asm volatile(
        "mma.sync.aligned.m16n8k8.row.col.f32.tf32.tf32.f32 "
        "{%0,%1,%2,%3}, {%4,%5,%6,%7}, {%8,%9}, {%0,%1,%2,%3};\n"
        : "+f"(d[0]), "+f"(d[1]), "+f"(d[2]), "+f"(d[3])
        : "r"(__float_as_uint(a[0])), "r"(__float_as_uint(a[1])),
          "r"(__float_as_uint(a[2])), "r"(__float_as_uint(a[3])),
          "r"(__float_as_uint(b[0])), "r"(__float_as_uint(b[1])));
}
__device__ __forceinline__ float sigm_(float x) { return 1.0f / (1.0f + __expf(-x)); }
__device__ __forceinline__ float tanh_(float x) {      // accurate (~1e-6), MUFU-based
    return 1.0f - 2.0f / (__expf(2.0f * x) + 1.0f);
}

// ---------------- generic tf32 GEMM: C[M,N] = A[M,K] @ B[N,K]^T + bias ----------------
#define BKg 32
__global__ __launch_bounds__(128) void gemm_tf32(
    const float* __restrict__ A, const float* __restrict__ Bw,
    const float* __restrict__ bias, float* __restrict__ C,
    int M, int N, int K)
{
    __shared__ float As[128][BKg + 4];
    __shared__ float Bs[128][BKg + 4];
    const int m0 = blockIdx.x * 128;
    const int n0 = blockIdx.y * 128;
    const int tid = threadIdx.x;
    const int warp = tid >> 5, lane = tid & 31;
    const int g = lane >> 2, tig = lane & 3;
    const int mw = (warp >> 1) * 64, nw = (warp & 1) * 64;

    float acc[4][8][4];
#pragma unroll
    for (int mi = 0; mi < 4; mi++)
#pragma unroll
        for (int ni = 0; ni < 8; ni++)
#pragma unroll
            for (int q = 0; q < 4; q++) acc[mi][ni][q] = 0.0f;

    const int kq = (tid & 7) * 4;
    const int rr = tid >> 3;

    for (int kt = 0; kt < K; kt += BKg) {
#pragma unroll
        for (int p = 0; p < 8; p++) {
            int r = rr + p * 16;
            float4 va = *(const float4*)(A + (size_t)(m0 + r) * K + kt + kq);
            As[r][kq + 0] = t32(va.x); As[r][kq + 1] = t32(va.y);
            As[r][kq + 2] = t32(va.z); As[r][kq + 3] = t32(va.w);
            float4 vb = *(const float4*)(Bw + (size_t)(n0 + r) * K + kt + kq);
            Bs[r][kq + 0] = t32(vb.x); Bs[r][kq + 1] = t32(vb.y);
            Bs[r][kq + 2] = t32(vb.z); Bs[r][kq + 3] = t32(vb.w);
        }
        __syncthreads();
#pragma unroll
        for (int kk = 0; kk < 4; kk++) {
            const int k0 = kk * 8;
            float a[4][4], b[8][2];
#pragma unroll
            for (int mi = 0; mi < 4; mi++) {
                int rb2 = mw + mi * 16;
                a[mi][0] = As[rb2 + g    ][k0 + tig];
                a[mi][1] = As[rb2 + g + 8][k0 + tig];
                a[mi][2] = As[rb2 + g    ][k0 + tig + 4];
                a[mi][3] = As[rb2 + g + 8][k0 + tig + 4];
            }
#pragma unroll
            for (int ni = 0; ni < 8; ni++) {
                int nb2 = nw + ni * 8;
                b[ni][0] = Bs[nb2 + g][k0 + tig];
                b[ni][1] = Bs[nb2 + g][k0 + tig + 4];
            }
#pragma unroll
            for (int mi = 0; mi < 4; mi++)
#pragma unroll
                for (int ni = 0; ni < 8; ni++)
                    mma_tf32(acc[mi][ni], a[mi], b[ni]);
        }
        __syncthreads();
    }
#pragma unroll
    for (int mi = 0; mi < 4; mi++) {
        int row = m0 + mw + mi * 16 + g;
#pragma unroll
        for (int ni = 0; ni < 8; ni++) {
            int col = n0 + nw + ni * 8 + 2 * tig;
            float bi0 = bias[col], bi1 = bias[col + 1];
            C[(size_t)row * N + col]           = acc[mi][ni][0] + bi0;
            C[(size_t)row * N + col + 1]       = acc[mi][ni][1] + bi1;
            C[(size_t)(row + 8) * N + col]     = acc[mi][ni][2] + bi0;
            C[(size_t)(row + 8) * N + col + 1] = acc[mi][ni][3] + bi1;
        }
    }
}

// ---------------- GRU recurrence (one layer) ----------------
// 128 blocks x 16 batch rows, 256 threads (8 warps). W_hh tf32-resident in smem.
// h kept as tf32 split (hi + lo) => fp32-accurate recurrent matvec: acc += W*hi + W*lo.
// mma: A = W_hh section (m=16 gates/warp, x3 sections r,z,n), B = h^T (n=8 batch rows x2).
#define GRU_SMEM_FLOATS (384*132 + 16*132 + 16*132 + 384)
__global__ __launch_bounds__(256) void gru_kernel(
    const float* __restrict__ xg, const float* __restrict__ h0,
    const float* __restrict__ w_hh, const float* __restrict__ b_hh,
    float* __restrict__ out, int ostride, int obase)
{
    extern __shared__ float smx[];
    float* ws  = smx;                 // [384][132] tf32 W_hh
    float* hhi = smx + 384 * 132;     // [16][132]  tf32 hi(h)
    float* hlo = hhi + 16 * 132;      // [16][132]  tf32 lo(h)
    float* bhh = hlo + 16 * 132;      // [384]

    const int tid = threadIdx.x;
    const int rb = blockIdx.x * 16;

    for (int i = tid; i < G_ * H_; i += 256) {
        int gi = i >> 7, k = i & 127;
        ws[gi * 132 + k] = t32(w_hh[i]);
    }
    for (int i = tid; i < 16 * H_; i += 256) {
        int r = i >> 7, k = i & 127;
        float v = h0[(size_t)(rb + r) * H_ + k];
        float hi = t32(v);
        hhi[r * 132 + k] = hi;
        hlo[r * 132 + k] = t32(v - hi);
    }
    for (int i = tid; i < G_; i += 256) bhh[i] = b_hh[i];
    __syncthreads();

    const int w = tid >> 5, lane = tid & 31;
    const int g = lane >> 2, tig = lane & 3;
    const int colb = 16 * w + g;
    // staged-store indices (coalesced y write)
    const int srow = tid >> 4;          // 0..15
    const int scol = (tid & 15) * 8;    // 0..120

    for (int t = 0; t < T_; t++) {
        // prefetch this step's input-gate preactivations (hidden under mma phase)
        float xv[2][2][2][3];
#pragma unroll
        for (int nt = 0; nt < 2; nt++)
#pragma unroll
            for (int rp = 0; rp < 2; rp++)
#pragma unroll
                for (int gp = 0; gp < 2; gp++) {
                    int row = 8 * nt + 2 * tig + rp;
                    int c = colb + 8 * gp;
                    size_t base = ((size_t)(rb + row) * T_ + t) * G_ + c;
                    xv[nt][rp][gp][0] = xg[base];
                    xv[nt][rp][gp][1] = xg[base + H_];
                    xv[nt][rp][gp][2] = xg[base + 2 * H_];
                }

        float acc[3][2][4];
#pragma unroll
        for (int s = 0; s < 3; s++)
#pragma unroll
            for (int nt = 0; nt < 2; nt++)
#pragma unroll
                for (int q = 0; q < 4; q++) acc[s][nt][q] = 0.0f;

#pragma unroll 4
        for (int ktile = 0; ktile < 16; ktile++) {
            const int k0 = ktile * 8;
            float a[3][4], bh[2][2], bl[2][2];
#pragma unroll
            for (int s = 0; s < 3; s++) {
                int gb = s * 128 + 16 * w;
                a[s][0] = ws[(gb + g    ) * 132 + k0 + tig];
                a[s][1] = ws[(gb + g + 8) * 132 + k0 + tig];
                a[s][2] = ws[(gb + g    ) * 132 + k0 + tig + 4];
                a[s][3] = ws[(gb + g + 8) * 132 + k0 + tig + 4];
            }
#pragma unroll
            for (int nt = 0; nt < 2; nt++) {
                int hb = (8 * nt + g) * 132 + k0;
                bh[nt][0] = hhi[hb + tig]; bh[nt][1] = hhi[hb + tig + 4];
                bl[nt][0] = hlo[hb + tig]; bl[nt][1] = hlo[hb + tig + 4];
            }
#pragma unroll
            for (int s = 0; s < 3; s++)
#pragma unroll
                for (int nt = 0; nt < 2; nt++) {
                    mma_tf32(acc[s][nt], a[s], bh[nt]);
                    mma_tf32(acc[s][nt], a[s], bl[nt]);
                }
        }
        __syncthreads();   // all hhi/hlo reads of step t complete

#pragma unroll
        for (int nt = 0; nt < 2; nt++)
#pragma unroll
            for (int fi = 0; fi < 4; fi++) {
                int rp = fi & 1, gp = fi >> 1;
                int row = 8 * nt + 2 * tig + rp;
                int col = colb + 8 * gp;
                int hidx = row * 132 + col;
                float hr = acc[0][nt][fi] + bhh[col];
                float hz = acc[1][nt][fi] + bhh[col + 128];
                float hn = acc[2][nt][fi] + bhh[col + 256];
                float r = sigm_(xv[nt][rp][gp][0] + hr);
                float z = sigm_(xv[nt][rp][gp][1] + hz);
                float n = tanh_(xv[nt][rp][gp][2] + r * hn);
                float hold = hhi[hidx] + hlo[hidx];
                float hnew = (1.0f - z) * n + z * hold;
                float hi = t32(hnew);
                hhi[hidx] = hi;
                hlo[hidx] = t32(hnew - hi);
            }
        __syncthreads();   // h(t) fully written

        // coalesced staged store of y_t (reconstruct fp32 from hi+lo)
        {
            float* o = out + (size_t)(rb + srow) * ostride + obase + (size_t)t * H_ + scol;
            const float* phi = hhi + srow * 132 + scol;
            const float* plo = hlo + srow * 132 + scol;
            float4 v0, v1;
            v0.x = phi[0] + plo[0]; v0.y = phi[1] + plo[1];
            v0.z = phi[2] + plo[2]; v0.w = phi[3] + plo[3];
            v1.x = phi[4] + plo[4]; v1.y = phi[5] + plo[5];
            v1.z = phi[6] + plo[6]; v1.w = phi[7] + plo[7];
            *(float4*)(o)     = v0;
            *(float4*)(o + 4) = v1;
        }
        // next step's mma reads hhi/hlo (read-only, safe to overlap with our reads);
        // the next epilogue's writes are fenced by the sync after its mma phase.
    }
}

// ---------------- LayerNorm(affine) + exact GELU ----------------
__global__ __launch_bounds__(256) void ln_gelu(
    const float* __restrict__ X, const float* __restrict__ gamma,
    const float* __restrict__ beta, float* __restrict__ Y, int N)
{
    __shared__ float red[16];
    const int row = blockIdx.x;
    const float* x = X + (size_t)row * N;
    float s = 0.0f, ss = 0.0f;
    for (int i = threadIdx.x; i < N; i += 256) {
        float v = x[i]; s += v; ss += v * v;
    }
#pragma unroll
    for (int o = 16; o > 0; o >>= 1) {
        s  += __shfl_xor_sync(0xffffffff, s, o);
        ss += __shfl_xor_sync(0xffffffff, ss, o);
    }
    int wid = threadIdx.x >> 5;
    if ((threadIdx.x & 31) == 0) { red[wid] = s; red[wid + 8] = ss; }
    __syncthreads();
    if (threadIdx.x == 0) {
        float ts = 0.0f, tss = 0.0f;
        for (int i = 0; i < 8; i++) { ts += red[i]; tss += red[i + 8]; }
        float mu = ts / N;
        red[0] = mu;
        float var = tss / N - mu * mu;
        red[1] = rsqrtf(var + 1e-5f);
    }
    __syncthreads();
    float mu = red[0], rstd = red[1];
    for (int i = threadIdx.x; i < N; i += 256) {
        float v = (x[i] - mu) * rstd * gamma[i] + beta[i];
        Y[(size_t)row * N + i] = v * normcdff(v);   // exact GELU
    }
}

// ---------------- copy user embeddings into concat cols [0,128) ----------------
__global__ void copy_user(const float* __restrict__ user, float* __restrict__ cat) {
    int i = blockIdx.x * blockDim.x + threadIdx.x;     // i < B_*DU_
    int b = i >> 7, c = i & 127;
    cat[(size_t)b * DIN_ + c] = user[i];
}

// ---------------- launch ----------------
extern "C" void kernel_launch(void* const* d_in, const int* in_sizes, int n_in,
                              void* d_out, int out_size)
{
    const float* user  = (const float*)d_in[0];
    const float* nbr   = (const float*)d_in[1];
    const float* h0    = (const float*)d_in[2];
    const float* w_ih0 = (const float*)d_in[3];
    const float* w_hh0 = (const float*)d_in[4];
    const float* b_ih0 = (const float*)d_in[5];
    const float* b_hh0 = (const float*)d_in[6];
    const float* w_ih1 = (const float*)d_in[7];
    const float* w_hh1 = (const float*)d_in[8];
    const float* b_ih1 = (const float*)d_in[9];
    const float* b_hh1 = (const float*)d_in[10];
    const float* W0 = (const float*)d_in[11];
    const float* b0 = (const float*)d_in[12];
    const float* g0 = (const float*)d_in[13];
    const float* be0 = (const float*)d_in[14];
    const float* W1 = (const float*)d_in[15];
    const float* b1 = (const float*)d_in[16];
    const float* g1 = (const float*)d_in[17];
    const float* be1 = (const float*)d_in[18];
    const float* W2 = (const float*)d_in[19];
    const float* b2 = (const float*)d_in[20];
    float* out = (float*)d_out;

    float *p_xg, *p_y, *p_cat, *p_a1, *p_a2;
    cudaGetSymbolAddress((void**)&p_xg,  g_xg);
    cudaGetSymbolAddress((void**)&p_y,   g_y);
    cudaGetSymbolAddress((void**)&p_cat, g_cat);
    cudaGetSymbolAddress((void**)&p_a1,  g_a1);
    cudaGetSymbolAddress((void**)&p_a2,  g_a2);
    cudaFuncSetAttribute(gru_kernel, cudaFuncAttributeMaxDynamicSharedMemorySize,
                         GRU_SMEM_FLOATS * 4);

    // user -> concat cols [0,128)
    copy_user<<<(B_ * DU_) / 256, 256>>>(user, p_cat);

    // layer-0 input gates: [BT,64] @ [384,64]^T
    gemm_tf32<<<dim3(BT_ / 128, 3), 128>>>(nbr, w_ih0, b_ih0, p_xg, BT_, G_, DI_);
    // layer-0 recurrence -> g_y
    gru_kernel<<<128, 256, GRU_SMEM_FLOATS * 4>>>(p_xg, h0, w_hh0, b_hh0,
                                                  p_y, T_ * H_, 0);
    // layer-1 input gates: [BT,128] @ [384,128]^T
    gemm_tf32<<<dim3(BT_ / 128, 3), 128>>>(p_y, w_ih1, b_ih1, p_xg, BT_, G_, H_);
    // layer-1 recurrence -> concat cols [128, 25728)
    gru_kernel<<<128, 256, GRU_SMEM_FLOATS * 4>>>(p_xg, h0 + (size_t)B_ * H_,
                                                  w_hh1, b_hh1, p_cat, DIN_, DU_);

    // MLP
    gemm_tf32<<<dim3(B_ / 128, 1024 / 128), 128>>>(p_cat, W0, b0, p_a1, B_, 1024, DIN_);
    ln_gelu<<<B_, 256>>>(p_a1, g0, be0, p_a1, 1024);
    gemm_tf32<<<dim3(B_ / 128, 512 / 128), 128>>>(p_a1, W1, b1, p_a2, B_, 512, 1024);
    ln_gelu<<<B_, 256>>>(p_a2, g1, be1, p_a2, 512);
    gemm_tf32<<<dim3(B_ / 128, 1), 128>>>(p_a2, W2, b2, out, B_, 128, 512);
}

// round 6
// speedup vs baseline: 1.1307x; 1.1307x over previous
#include <cuda_runtime.h>
#include <cstdint>
#include <cstddef>

#define B_   2048
#define T_   200
#define DI_  64
#define H_   128
#define G_   384
#define DU_  128
#define DIN_ 25728
#define BT_  (B_*T_)

// ---------------- device-global scratch ----------------
__device__ float g_xg[(size_t)BT_ * G_];     // gate preactivations, layout [T][B][G]
__device__ float g_y[(size_t)BT_ * H_];      // layer-0 GRU output, layout [T][B][H]
__device__ float g_cat[(size_t)B_ * DIN_];   // [user | flat(y1)]
__device__ float g_a1[(size_t)B_ * 1024];
__device__ float g_a2[(size_t)B_ * 512];

// ---------------- helpers ----------------
__device__ __forceinline__ float t32(float x) {
    uint32_t u; asm("cvt.rna.tf32.f32 %0, %1;" : "=r"(u) : "f"(x));
    return __uint_as_float(u);
}
__device__ __forceinline__ void mma_tf32(float* d, const float* a, const float* b) {
    asm volatile(
        "mma.sync.aligned.m16n8k8.row.col.f32.tf32.tf32.f32 "
        "{%0,%1,%2,%3}, {%4,%5,%6,%7}, {%8,%9}, {%0,%1,%2,%3};\n"
        : "+f"(d[0]), "+f"(d[1]), "+f"(d[2]), "+f"(d[3])
        : "r"(__float_as_uint(a[0])), "r"(__float_as_uint(a[1])),
          "r"(__float_as_uint(a[2])), "r"(__float_as_uint(a[3])),
          "r"(__float_as_uint(b[0])), "r"(__float_as_uint(b[1])));
}
__device__ __forceinline__ float sigm_(float x) {
    float e = __expf(-x);
    return __fdividef(1.0f, 1.0f + e);
}
__device__ __forceinline__ float tanh_(float x) {      // accurate (~1e-6)
    float e = __expf(2.0f * x);
    return 1.0f - __fdividef(2.0f, e + 1.0f);
}
__device__ __forceinline__ uint32_t sm_u32(const void* p) {
    uint32_t a;
    asm("{ .reg .u64 t; cvta.to.shared.u64 t, %1; cvt.u32.u64 %0, t; }" : "=r"(a) : "l"(p));
    return a;
}
__device__ __forceinline__ void cp16(uint32_t dst, const void* src) {
    asm volatile("cp.async.cg.shared.global [%0], [%1], 16;\n" :: "r"(dst), "l"(src));
}
__device__ __forceinline__ void cp_commit() { asm volatile("cp.async.commit_group;\n"); }
template<int N> __device__ __forceinline__ void cp_wait() {
    asm volatile("cp.async.wait_group %0;\n" :: "n"(N));
}

// ---------------- GEMM v2: C[M,N] = A[M,K] @ B[N,K]^T + bias ----------------
// BM=128, BN=64, BK=32, 256 threads (8 warps, 4m x 2n, warp tile 32x32),
// cp.async double-buffered smem, tf32 RN-convert at fragment load.
// permute=1: output row m -> (m % T_)*B_ + m/T_   (writes [T][B][*] layout)
#define GEMM_SMEM_BYTES ((2*128*36 + 2*64*36) * 4)
__global__ __launch_bounds__(256) void gemm2(
    const float* __restrict__ A, const float* __restrict__ Bw,
    const float* __restrict__ bias, float* __restrict__ C,
    int M, int N, int K, int permute)
{
    extern __shared__ float sm[];
    float* As = sm;               // [2][128][36]
    float* Bs = sm + 2*128*36;    // [2][64][36]
    const int m0 = blockIdx.x * 128;
    const int n0 = blockIdx.y * 64;
    const int tid = threadIdx.x;
    const int warp = tid >> 5, lane = tid & 31;
    const int g = lane >> 2, tig = lane & 3;
    const int mw = (warp >> 1) * 32, nw = (warp & 1) * 32;

    const int rowA = tid >> 1, cA = (tid & 1) * 16;  // 4 float4 per thread (A)
    const int rowB = tid >> 2, cB = (tid & 3) * 8;   // 2 float4 per thread (B)

    const uint32_t sAsm = sm_u32(As);
    const uint32_t sBsm = sm_u32(Bs);

    float acc[2][4][4];
#pragma unroll
    for (int mi = 0; mi < 2; mi++)
#pragma unroll
        for (int ni = 0; ni < 4; ni++)
#pragma unroll
            for (int q = 0; q < 4; q++) acc[mi][ni][q] = 0.0f;

    const int nk = K / 32;
    {   // prologue: stage 0
        const float* pa = A + (size_t)(m0 + rowA) * K + cA;
        uint32_t da = sAsm + (rowA * 36 + cA) * 4;
#pragma unroll
        for (int q = 0; q < 4; q++) cp16(da + q * 16, pa + q * 4);
        const float* pb = Bw + (size_t)(n0 + rowB) * K + cB;
        uint32_t db = sBsm + (rowB * 36 + cB) * 4;
#pragma unroll
        for (int q = 0; q < 2; q++) cp16(db + q * 16, pb + q * 4);
        cp_commit();
    }
    for (int kt = 0; kt < nk; kt++) {
        if (kt + 1 < nk) {
            const int koff = (kt + 1) * 32;
            const int bo = (kt + 1) & 1;
            const float* pa = A + (size_t)(m0 + rowA) * K + koff + cA;
            uint32_t da = sAsm + (bo * 128 * 36 + rowA * 36 + cA) * 4;
#pragma unroll
            for (int q = 0; q < 4; q++) cp16(da + q * 16, pa + q * 4);
            const float* pb = Bw + (size_t)(n0 + rowB) * K + koff + cB;
            uint32_t db = sBsm + (bo * 64 * 36 + rowB * 36 + cB) * 4;
#pragma unroll
            for (int q = 0; q < 2; q++) cp16(db + q * 16, pb + q * 4);
        }
        cp_commit();
        cp_wait<1>();
        __syncthreads();
        const float* Ab = As + (kt & 1) * 128 * 36;
        const float* Bb = Bs + (kt & 1) * 64 * 36;
#pragma unroll
        for (int kk = 0; kk < 4; kk++) {
            const int k0 = kk * 8;
            float a[2][4], b[4][2];
#pragma unroll
            for (int mi = 0; mi < 2; mi++) {
                int r = mw + mi * 16;
                a[mi][0] = t32(Ab[(r + g    ) * 36 + k0 + tig]);
                a[mi][1] = t32(Ab[(r + g + 8) * 36 + k0 + tig]);
                a[mi][2] = t32(Ab[(r + g    ) * 36 + k0 + tig + 4]);
                a[mi][3] = t32(Ab[(r + g + 8) * 36 + k0 + tig + 4]);
            }
#pragma unroll
            for (int ni = 0; ni < 4; ni++) {
                int r = nw + ni * 8 + g;
                b[ni][0] = t32(Bb[r * 36 + k0 + tig]);
                b[ni][1] = t32(Bb[r * 36 + k0 + tig + 4]);
            }
#pragma unroll
            for (int mi = 0; mi < 2; mi++)
#pragma unroll
                for (int ni = 0; ni < 4; ni++)
                    mma_tf32(acc[mi][ni], a[mi], b[ni]);
        }
        __syncthreads();
    }
    // epilogue
#pragma unroll
    for (int mi = 0; mi < 2; mi++) {
#pragma unroll
        for (int half = 0; half < 2; half++) {
            int m = m0 + mw + mi * 16 + g + half * 8;
            size_t ro;
            if (permute) { int tt = m % T_; int bb = m / T_; ro = (size_t)tt * B_ + bb; }
            else ro = (size_t)m;
#pragma unroll
            for (int ni = 0; ni < 4; ni++) {
                int col = n0 + nw + ni * 8 + 2 * tig;
                float* p = C + ro * (size_t)N + col;
                p[0] = acc[mi][ni][half ? 2 : 0] + bias[col];
                p[1] = acc[mi][ni][half ? 3 : 1] + bias[col + 1];
            }
        }
    }
}

// ---------------- GRU v2b ----------------
// 128 blocks x 16 batch rows, 256 threads (8 warps).
// W_hh sections r,z in REGISTERS (128 floats/thread); section n in smem
// (conflict-free, stride 132). h as tf32 split hi+lo in ping-pong smem buffers.
// xg ([T][B][G]) staged via cp.async double buffer; y stored coalesced.
#define GRU_XS (16 * 388)   // one xg stage buffer (floats)
#define GRU_HB (16 * 132)   // one h buffer (floats)
#define GRU_SMEM_BYTES ((2 * GRU_XS + 4 * GRU_HB + 128 * 132) * 4)
__global__ __launch_bounds__(256, 1) void gru2(
    const float* __restrict__ xg,     // [T][B][G]
    const float* __restrict__ h0,     // [B][H]
    const float* __restrict__ w_hh, const float* __restrict__ b_hh,
    float* __restrict__ out, int mode)  // mode 0: y [T][B][H];  mode 1: g_cat
{
    extern __shared__ float sm[];
    float* xs = sm;                    // [2][16][388]
    float* hi = sm + 2 * GRU_XS;       // [2][16][132]
    float* lo = hi + 2 * GRU_HB;       // [2][16][132]
    float* wn = lo + 2 * GRU_HB;       // [128][132] tf32 W_hh section n

    const int tid = threadIdx.x;
    const int rb = blockIdx.x * 16;
    const int w = tid >> 5, lane = tid & 31;
    const int g = lane >> 2, tig = lane & 3;
    const int colb = 16 * w + g;

    // W_hh sections r,z -> registers (tf32); L2-served across the 128 blocks.
    float wreg[2][16][4];
#pragma unroll
    for (int s = 0; s < 2; s++)
#pragma unroll
        for (int kt = 0; kt < 16; kt++) {
            const float* p = w_hh + (size_t)(s * 128 + 16 * w + g) * H_ + kt * 8 + tig;
            wreg[s][kt][0] = t32(p[0]);
            wreg[s][kt][1] = t32(p[8 * H_]);
            wreg[s][kt][2] = t32(p[4]);
            wreg[s][kt][3] = t32(p[8 * H_ + 4]);
        }
    // section n -> smem
    for (int i = tid; i < H_ * H_; i += 256) {
        int gi = i >> 7, k = i & 127;
        wn[gi * 132 + k] = t32(w_hh[(size_t)(256 + gi) * H_ + k]);
    }
    const float bh_r0 = b_hh[colb],       bh_r1 = b_hh[colb + 8];
    const float bh_z0 = b_hh[128 + colb], bh_z1 = b_hh[128 + colb + 8];
    const float bh_n0 = b_hh[256 + colb], bh_n1 = b_hh[256 + colb + 8];

    // h0 -> buffer 0
    for (int i = tid; i < 16 * H_; i += 256) {
        int r = i >> 7, k = i & 127;
        float v = h0[(size_t)(rb + r) * H_ + k];
        float h_ = t32(v);
        hi[r * 132 + k] = h_;
        lo[r * 132 + k] = t32(v - h_);
    }
    const uint32_t xs_sm = sm_u32(xs);
    {   // prologue: stage xg for t=0
        const float* src = xg + ((size_t)0 * B_ + rb) * G_;
#pragma unroll
        for (int q = 0; q < 6; q++) {
            int i = tid + q * 256;                 // float4 index, 0..1535
            int r = i / 96, c4 = i % 96;
            cp16(xs_sm + (r * 388 + c4 * 4) * 4, src + (size_t)i * 4);
        }
        cp_commit();
    }
    __syncthreads();

    const int srow = tid >> 4, scol = (tid & 15) * 8;

    for (int t = 0; t < T_; t++) {
        const int p = t & 1;
        // issue next step's xg stage (hidden under the mma phase)
        if (t + 1 < T_) {
            const float* src = xg + ((size_t)(t + 1) * B_ + rb) * G_;
            uint32_t dst = xs_sm + (uint32_t)(((t + 1) & 1) * GRU_XS * 4);
#pragma unroll
            for (int q = 0; q < 6; q++) {
                int i = tid + q * 256;
                int r = i / 96, c4 = i % 96;
                cp16(dst + (r * 388 + c4 * 4) * 4, src + (size_t)i * 4);
            }
        }
        cp_commit();

        float acc[3][2][4];
#pragma unroll
        for (int s = 0; s < 3; s++)
#pragma unroll
            for (int nt = 0; nt < 2; nt++)
#pragma unroll
                for (int q = 0; q < 4; q++) acc[s][nt][q] = 0.0f;

        const float* hib = hi + p * GRU_HB;
        const float* lob = lo + p * GRU_HB;
#pragma unroll
        for (int kt = 0; kt < 16; kt++) {
            const int k0 = kt * 8;
            float bh[2][2], bl[2][2], an[4];
#pragma unroll
            for (int nt = 0; nt < 2; nt++) {
                int hb = (8 * nt + g) * 132 + k0;
                bh[nt][0] = hib[hb + tig]; bh[nt][1] = hib[hb + tig + 4];
                bl[nt][0] = lob[hb + tig]; bl[nt][1] = lob[hb + tig + 4];
            }
            an[0] = wn[(colb    ) * 132 + k0 + tig];
            an[1] = wn[(colb + 8) * 132 + k0 + tig];
            an[2] = wn[(colb    ) * 132 + k0 + tig + 4];
            an[3] = wn[(colb + 8) * 132 + k0 + tig + 4];
#pragma unroll
            for (int nt = 0; nt < 2; nt++) {
                mma_tf32(acc[0][nt], wreg[0][kt], bh[nt]);
                mma_tf32(acc[0][nt], wreg[0][kt], bl[nt]);
                mma_tf32(acc[1][nt], wreg[1][kt], bh[nt]);
                mma_tf32(acc[1][nt], wreg[1][kt], bl[nt]);
                mma_tf32(acc[2][nt], an, bh[nt]);
                mma_tf32(acc[2][nt], an, bl[nt]);
            }
        }
        cp_wait<1>();
        __syncthreads();   // xs[t&1] visible to all; h reads of buf p complete

        const float* xb = xs + p * GRU_XS;
        float* hiw = hi + (p ^ 1) * GRU_HB;
        float* low = lo + (p ^ 1) * GRU_HB;
#pragma unroll
        for (int nt = 0; nt < 2; nt++)
#pragma unroll
            for (int fi = 0; fi < 4; fi++) {
                int rp = fi & 1, gp = fi >> 1;
                int row = 8 * nt + 2 * tig + rp;
                int col = colb + 8 * gp;
                int hidx = row * 132 + col;
                const float* xr = xb + row * 388 + col;
                float hr = acc[0][nt][fi] + (gp ? bh_r1 : bh_r0);
                float hz = acc[1][nt][fi] + (gp ? bh_z1 : bh_z0);
                float hn = acc[2][nt][fi] + (gp ? bh_n1 : bh_n0);
                float r = sigm_(xr[0]   + hr);
                float z = sigm_(xr[128] + hz);
                float n = tanh_(xr[256] + r * hn);
                float hold = hib[hidx] + lob[hidx];
                float hnew = (1.0f - z) * n + z * hold;
                float h_ = t32(hnew);
                hiw[hidx] = h_;
                low[hidx] = t32(hnew - h_);
            }
        __syncthreads();   // h(t) written before y store / next mma

        // coalesced y_t store
        {
            const float* ph = hi + (p ^ 1) * GRU_HB + srow * 132 + scol;
            const float* pl = lo + (p ^ 1) * GRU_HB + srow * 132 + scol;
            float* o;
            if (mode == 0) o = out + ((size_t)t * B_ + rb + srow) * H_ + scol;
            else           o = out + (size_t)(rb + srow) * DIN_ + DU_ + (size_t)t * H_ + scol;
            float4 v0, v1;
            v0.x = ph[0] + pl[0]; v0.y = ph[1] + pl[1];
            v0.z = ph[2] + pl[2]; v0.w = ph[3] + pl[3];
            v1.x = ph[4] + pl[4]; v1.y = ph[5] + pl[5];
            v1.z = ph[6] + pl[6]; v1.w = ph[7] + pl[7];
            *(float4*)(o)     = v0;
            *(float4*)(o + 4) = v1;
        }
    }
}

// ---------------- LayerNorm(affine) + exact GELU ----------------
__global__ __launch_bounds__(256) void ln_gelu(
    const float* __restrict__ X, const float* __restrict__ gamma,
    const float* __restrict__ beta, float* __restrict__ Y, int N)
{
    __shared__ float red[16];
    const int row = blockIdx.x;
    const float* x = X + (size_t)row * N;
    float s = 0.0f, ss = 0.0f;
    for (int i = threadIdx.x; i < N; i += 256) {
        float v = x[i]; s += v; ss += v * v;
    }
#pragma unroll
    for (int o = 16; o > 0; o >>= 1) {
        s  += __shfl_xor_sync(0xffffffff, s, o);
        ss += __shfl_xor_sync(0xffffffff, ss, o);
    }
    int wid = threadIdx.x >> 5;
    if ((threadIdx.x & 31) == 0) { red[wid] = s; red[wid + 8] = ss; }
    __syncthreads();
    if (threadIdx.x == 0) {
        float ts = 0.0f, tss = 0.0f;
        for (int i = 0; i < 8; i++) { ts += red[i]; tss += red[i + 8]; }
        float mu = ts / N;
        red[0] = mu;
        float var = tss / N - mu * mu;
        red[1] = rsqrtf(var + 1e-5f);
    }
    __syncthreads();
    float mu = red[0], rstd = red[1];
    for (int i = threadIdx.x; i < N; i += 256) {
        float v = (x[i] - mu) * rstd * gamma[i] + beta[i];
        Y[(size_t)row * N + i] = v * normcdff(v);   // exact GELU
    }
}

// ---------------- copy user embeddings into concat cols [0,128) ----------------
__global__ void copy_user(const float* __restrict__ user, float* __restrict__ cat) {
    int i = blockIdx.x * blockDim.x + threadIdx.x;
    int b = i >> 7, c = i & 127;
    cat[(size_t)b * DIN_ + c] = user[i];
}

// ---------------- launch ----------------
extern "C" void kernel_launch(void* const* d_in, const int* in_sizes, int n_in,
                              void* d_out, int out_size)
{
    const float* user  = (const float*)d_in[0];
    const float* nbr   = (const float*)d_in[1];
    const float* h0    = (const float*)d_in[2];
    const float* w_ih0 = (const float*)d_in[3];
    const float* w_hh0 = (const float*)d_in[4];
    const float* b_ih0 = (const float*)d_in[5];
    const float* b_hh0 = (const float*)d_in[6];
    const float* w_ih1 = (const float*)d_in[7];
    const float* w_hh1 = (const float*)d_in[8];
    const float* b_ih1 = (const float*)d_in[9];
    const float* b_hh1 = (const float*)d_in[10];
    const float* W0 = (const float*)d_in[11];
    const float* b0 = (const float*)d_in[12];
    const float* g0 = (const float*)d_in[13];
    const float* be0 = (const float*)d_in[14];
    const float* W1 = (const float*)d_in[15];
    const float* b1 = (const float*)d_in[16];
    const float* g1 = (const float*)d_in[17];
    const float* be1 = (const float*)d_in[18];
    const float* W2 = (const float*)d_in[19];
    const float* b2 = (const float*)d_in[20];
    float* out = (float*)d_out;

    float *p_xg, *p_y, *p_cat, *p_a1, *p_a2;
    cudaGetSymbolAddress((void**)&p_xg,  g_xg);
    cudaGetSymbolAddress((void**)&p_y,   g_y);
    cudaGetSymbolAddress((void**)&p_cat, g_cat);
    cudaGetSymbolAddress((void**)&p_a1,  g_a1);
    cudaGetSymbolAddress((void**)&p_a2,  g_a2);
    cudaFuncSetAttribute(gemm2, cudaFuncAttributeMaxDynamicSharedMemorySize, GEMM_SMEM_BYTES);
    cudaFuncSetAttribute(gru2,  cudaFuncAttributeMaxDynamicSharedMemorySize, GRU_SMEM_BYTES);

    copy_user<<<(B_ * DU_) / 256, 256>>>(user, p_cat);

    // layer-0 input gates: [BT,64]@[384,64]^T -> xg [T][B][G] (permuted rows)
    gemm2<<<dim3(BT_ / 128, G_ / 64), 256, GEMM_SMEM_BYTES>>>(
        nbr, w_ih0, b_ih0, p_xg, BT_, G_, DI_, 1);
    // layer-0 recurrence -> y [T][B][H]
    gru2<<<128, 256, GRU_SMEM_BYTES>>>(p_xg, h0, w_hh0, b_hh0, p_y, 0);
    // layer-1 input gates: rows already (t*B+b) -> identity row map
    gemm2<<<dim3(BT_ / 128, G_ / 64), 256, GEMM_SMEM_BYTES>>>(
        p_y, w_ih1, b_ih1, p_xg, BT_, G_, H_, 0);
    // layer-1 recurrence -> g_cat cols [128, 25728)
    gru2<<<128, 256, GRU_SMEM_BYTES>>>(p_xg, h0 + (size_t)B_ * H_, w_hh1, b_hh1, p_cat, 1);

    // MLP
    gemm2<<<dim3(B_ / 128, 1024 / 64), 256, GEMM_SMEM_BYTES>>>(
        p_cat, W0, b0, p_a1, B_, 1024, DIN_, 0);
    ln_gelu<<<B_, 256>>>(p_a1, g0, be0, p_a1, 1024);
    gemm2<<<dim3(B_ / 128, 512 / 64), 256, GEMM_SMEM_BYTES>>>(
        p_a1, W1, b1, p_a2, B_, 512, 1024, 0);
    ln_gelu<<<B_, 256>>>(p_a2, g1, be1, p_a2, 512);
    gemm2<<<dim3(B_ / 128, 128 / 64), 256, GEMM_SMEM_BYTES>>>(
        p_a2, W2, b2, out, B_, 128, 512, 0);
}